// round 1
// baseline (speedup 1.0000x reference)
#include <cuda_runtime.h>
#include <math.h>

// ---------------- problem constants ----------------
#define BATCH   2
#define L_SEQ   512
#define DM      768
#define DI      1536
#define NSTATE  16
#define RRANK   48
#define KCONV   4
#define NLAYER  4
#define VOCAB   50280
#define M_ROWS  (BATCH * L_SEQ)        // 1024
#define PROJ_N  (RRANK + 2 * NSTATE)   // 80

// ---------------- scratch (device globals; no allocations allowed) ----------------
__device__ float g_h   [M_ROWS * DM];        // residual stream
__device__ float g_r   [M_ROWS * DM];        // rmsnorm output
__device__ float g_xz  [M_ROWS * 2 * DI];    // in_proj output
__device__ float g_xc  [M_ROWS * DI];        // conv+silu output
__device__ float g_proj[M_ROWS * PROJ_N];    // x_proj output (dt_r | B | C)
__device__ float g_dt  [M_ROWS * DI];        // dt after softplus
__device__ float g_y   [M_ROWS * DI];        // scan output (gated)

// ---------------- embed gather ----------------
__global__ void embed_kernel(const int* __restrict__ ids, const int* __restrict__ mask,
                             const float* __restrict__ embed, float* __restrict__ h) {
    int i = blockIdx.x * blockDim.x + threadIdx.x;
    if (i >= M_ROWS * DM) return;
    int row = i / DM, d = i % DM;
    float m = (float)mask[row];
    h[i] = embed[(size_t)ids[row] * DM + d] * m;
}

// ---------------- rmsnorm (one block per row of 768) ----------------
__global__ void rmsnorm_kernel(const float* __restrict__ x, const float* __restrict__ w,
                               float* __restrict__ out) {
    int row = blockIdx.x;
    const float* xr = x + (size_t)row * DM;
    float s = 0.f;
    for (int d = threadIdx.x; d < DM; d += 256) { float v = xr[d]; s += v * v; }
    #pragma unroll
    for (int o = 16; o; o >>= 1) s += __shfl_xor_sync(0xffffffffu, s, o);
    __shared__ float sm[8];
    __shared__ float s_inv;
    if ((threadIdx.x & 31) == 0) sm[threadIdx.x >> 5] = s;
    __syncthreads();
    if (threadIdx.x == 0) {
        float t = 0.f;
        #pragma unroll
        for (int i = 0; i < 8; i++) t += sm[i];
        s_inv = rsqrtf(t / (float)DM + 1e-5f);
    }
    __syncthreads();
    float inv = s_inv;
    for (int d = threadIdx.x; d < DM; d += 256)
        out[(size_t)row * DM + d] = xr[d] * inv * w[d];
}

// ---------------- SGEMM NT: C[M,N] (+)= A[M,K] * B[N,K]^T ----------------
// BM=128 BN=64 BK=16, 256 threads, 8x4 per thread. K % 16 == 0, M % 128 == 0 assumed.
template <bool ADD>
__global__ void __launch_bounds__(256)
sgemm_nt(const float* __restrict__ A, const float* __restrict__ B,
         float* __restrict__ C, int M, int N, int Kdim,
         int lda, int ldb, int ldc) {
    __shared__ float As[16][128];
    __shared__ float Bs[16][64 + 4];
    int bm = blockIdx.y * 128;
    int bn = blockIdx.x * 64;
    int tid = threadIdx.x;
    int tx = tid & 15;        // N direction (x4)
    int ty = tid >> 4;        // M direction (x8)
    float acc[8][4];
    #pragma unroll
    for (int i = 0; i < 8; i++)
        #pragma unroll
        for (int j = 0; j < 4; j++) acc[i][j] = 0.f;

    for (int k0 = 0; k0 < Kdim; k0 += 16) {
        // A tile: 128x16 = 512 float4s, 2 per thread
        #pragma unroll
        for (int it = 0; it < 2; it++) {
            int i = tid + it * 256;
            int r = i >> 2, c4 = (i & 3) * 4;
            float4 v = *(const float4*)(A + (size_t)(bm + r) * lda + k0 + c4);
            As[c4 + 0][r] = v.x; As[c4 + 1][r] = v.y;
            As[c4 + 2][r] = v.z; As[c4 + 3][r] = v.w;
        }
        // B tile: 64x16 = 256 float4s, 1 per thread
        {
            int r = tid >> 2, c4 = (tid & 3) * 4;
            float4 v = make_float4(0.f, 0.f, 0.f, 0.f);
            if (bn + r < N)
                v = *(const float4*)(B + (size_t)(bn + r) * ldb + k0 + c4);
            Bs[c4 + 0][r] = v.x; Bs[c4 + 1][r] = v.y;
            Bs[c4 + 2][r] = v.z; Bs[c4 + 3][r] = v.w;
        }
        __syncthreads();
        #pragma unroll
        for (int c = 0; c < 16; c++) {
            float ra[8], rb[4];
            #pragma unroll
            for (int i = 0; i < 8; i++) ra[i] = As[c][ty * 8 + i];
            #pragma unroll
            for (int j = 0; j < 4; j++) rb[j] = Bs[c][tx * 4 + j];
            #pragma unroll
            for (int i = 0; i < 8; i++)
                #pragma unroll
                for (int j = 0; j < 4; j++)
                    acc[i][j] += ra[i] * rb[j];
        }
        __syncthreads();
    }

    #pragma unroll
    for (int i = 0; i < 8; i++) {
        int row = bm + ty * 8 + i;
        #pragma unroll
        for (int j = 0; j < 4; j++) {
            int col = bn + tx * 4 + j;
            if (col < N) {
                size_t idx = (size_t)row * ldc + col;
                if (ADD) C[idx] += acc[i][j];
                else     C[idx]  = acc[i][j];
            }
        }
    }
}

// ---------------- depthwise causal conv (K=4) + SiLU ----------------
__global__ void conv_silu_kernel(const float* __restrict__ xz, const float* __restrict__ cw,
                                 const float* __restrict__ cb, float* __restrict__ xc) {
    int i = blockIdx.x * blockDim.x + threadIdx.x;
    if (i >= M_ROWS * DI) return;
    int row = i / DI, d = i % DI;
    int b = row / L_SEQ, l = row % L_SEQ;
    float acc = cb[d];
    #pragma unroll
    for (int k = 0; k < KCONV; k++) {
        int ll = l - (KCONV - 1) + k;
        if (ll >= 0)
            acc += cw[d * KCONV + k] * xz[(size_t)(b * L_SEQ + ll) * (2 * DI) + d];
    }
    xc[i] = acc / (1.f + __expf(-acc));   // silu
}

// ---------------- dt bias + softplus ----------------
__global__ void dt_softplus_kernel(float* __restrict__ dt, const float* __restrict__ dtb) {
    int i = blockIdx.x * blockDim.x + threadIdx.x;
    if (i >= M_ROWS * DI) return;
    int d = i % DI;
    float v = dt[i] + dtb[d];
    dt[i] = (v > 20.f) ? v : log1pf(__expf(v));
}

// ---------------- SSM scan: one 16-lane group per (b, d) channel ----------------
__global__ void scan_kernel(const float* __restrict__ dt, const float* __restrict__ xc,
                            const float* __restrict__ proj, const float* __restrict__ xz,
                            const float* __restrict__ A_log, const float* __restrict__ Dp,
                            float* __restrict__ y) {
    int gid = (blockIdx.x * blockDim.x + threadIdx.x) >> 4;  // group id = b*DI + d
    int n = threadIdx.x & 15;
    if (gid >= BATCH * DI) return;
    int b = gid / DI, d = gid % DI;
    float A = -__expf(A_log[d * NSTATE + n]);
    float Dval = Dp[d];
    float h = 0.f;
    for (int l = 0; l < L_SEQ; l++) {
        size_t row = (size_t)b * L_SEQ + l;
        float dtv = dt[row * DI + d];
        float xv  = xc[row * DI + d];
        float Bv  = proj[row * PROJ_N + RRANK + n];
        float Cv  = proj[row * PROJ_N + RRANK + NSTATE + n];
        h = __expf(dtv * A) * h + dtv * Bv * xv;
        float p = h * Cv;
        p += __shfl_xor_sync(0xffffffffu, p, 1);
        p += __shfl_xor_sync(0xffffffffu, p, 2);
        p += __shfl_xor_sync(0xffffffffu, p, 4);
        p += __shfl_xor_sync(0xffffffffu, p, 8);
        if (n == 0) {
            float zv = xz[row * (2 * DI) + DI + d];
            float yv = p + Dval * xv;
            y[row * DI + d] = yv * (zv / (1.f + __expf(-zv)));   // * silu(z)
        }
    }
}

// ---------------- host orchestration ----------------
extern "C" void kernel_launch(void* const* d_in, const int* in_sizes, int n_in,
                              void* d_out, int out_size) {
    const int*   q_ids   = (const int*)d_in[0];
    const int*   q_mask  = (const int*)d_in[1];
    // d_in[2], d_in[3]: answer ids/mask — unused by the reference
    const float* embed   = (const float*)d_in[4];
    const float* in_w    = (const float*)d_in[5];
    const float* conv_w  = (const float*)d_in[6];
    const float* conv_b  = (const float*)d_in[7];
    const float* x_w     = (const float*)d_in[8];
    const float* dt_w    = (const float*)d_in[9];
    const float* dt_b    = (const float*)d_in[10];
    const float* A_log   = (const float*)d_in[11];
    const float* Dp      = (const float*)d_in[12];
    const float* out_w   = (const float*)d_in[13];
    const float* norm_w  = (const float*)d_in[14];
    const float* fnorm_w = (const float*)d_in[15];
    float* out = (float*)d_out;

    float *h, *r, *xz, *xc, *proj, *dt, *y;
    cudaGetSymbolAddress((void**)&h,    g_h);
    cudaGetSymbolAddress((void**)&r,    g_r);
    cudaGetSymbolAddress((void**)&xz,   g_xz);
    cudaGetSymbolAddress((void**)&xc,   g_xc);
    cudaGetSymbolAddress((void**)&proj, g_proj);
    cudaGetSymbolAddress((void**)&dt,   g_dt);
    cudaGetSymbolAddress((void**)&y,    g_y);

    // embedding gather
    embed_kernel<<<(M_ROWS * DM + 255) / 256, 256>>>(q_ids, q_mask, embed, h);

    for (int l = 0; l < NLAYER; l++) {
        const float* in_w_l  = in_w  + (size_t)l * (2 * DI) * DM;
        const float* cw_l    = conv_w + (size_t)l * DI * KCONV;
        const float* cb_l    = conv_b + (size_t)l * DI;
        const float* x_w_l   = x_w   + (size_t)l * PROJ_N * DI;
        const float* dt_w_l  = dt_w  + (size_t)l * DI * RRANK;
        const float* dt_b_l  = dt_b  + (size_t)l * DI;
        const float* A_log_l = A_log + (size_t)l * DI * NSTATE;
        const float* Dp_l    = Dp    + (size_t)l * DI;
        const float* out_w_l = out_w + (size_t)l * DM * DI;
        const float* norm_l  = norm_w + (size_t)l * DM;

        // r = rmsnorm(h)
        rmsnorm_kernel<<<M_ROWS, 256>>>(h, norm_l, r);

        // xz = r @ in_w^T  (1024 x 3072, K=768)
        sgemm_nt<false><<<dim3((2 * DI + 63) / 64, M_ROWS / 128), 256>>>(
            r, in_w_l, xz, M_ROWS, 2 * DI, DM, DM, DM, 2 * DI);

        // xc = silu(conv(x) + b)
        conv_silu_kernel<<<(M_ROWS * DI + 255) / 256, 256>>>(xz, cw_l, cb_l, xc);

        // proj = xc @ x_w^T  (1024 x 80, K=1536)
        sgemm_nt<false><<<dim3((PROJ_N + 63) / 64, M_ROWS / 128), 256>>>(
            xc, x_w_l, proj, M_ROWS, PROJ_N, DI, DI, DI, PROJ_N);

        // dt = proj[:, :48] @ dt_w^T  (1024 x 1536, K=48)
        sgemm_nt<false><<<dim3((DI + 63) / 64, M_ROWS / 128), 256>>>(
            proj, dt_w_l, dt, M_ROWS, DI, RRANK, PROJ_N, RRANK, DI);

        // dt = softplus(dt + dt_b)
        dt_softplus_kernel<<<(M_ROWS * DI + 255) / 256, 256>>>(dt, dt_b_l);

        // y = scan(...) * silu(z)  (+ Dp * x)
        scan_kernel<<<(BATCH * DI * 16 + 255) / 256, 256>>>(
            dt, xc, proj, xz, A_log_l, Dp_l, y);

        // h += y @ out_w^T  (1024 x 768, K=1536)
        sgemm_nt<true><<<dim3((DM + 63) / 64, M_ROWS / 128), 256>>>(
            y, out_w_l, h, M_ROWS, DM, DI, DI, DI, DM);
    }

    // final rmsnorm
    rmsnorm_kernel<<<M_ROWS, 256>>>(h, fnorm_w, r);

    // logits = r @ embed^T  (1024 x 50280, K=768)
    sgemm_nt<false><<<dim3((VOCAB + 63) / 64, M_ROWS / 128), 256>>>(
        r, embed, out, M_ROWS, VOCAB, DM, DM, DM, VOCAB);
}

// round 3
// speedup vs baseline: 1.9085x; 1.9085x over previous
#include <cuda_runtime.h>
#include <math.h>
#include <stdint.h>

// ---------------- problem constants ----------------
#define BATCH   2
#define L_SEQ   512
#define DM      768
#define DI      1536
#define NSTATE  16
#define RRANK   48
#define KCONV   4
#define NLAYER  4
#define VOCAB   50280
#define M_ROWS  (BATCH * L_SEQ)        // 1024
#define PROJ_N  (RRANK + 2 * NSTATE)   // 80

// ---------------- scratch (device globals) ----------------
__device__ float g_h   [M_ROWS * DM];
__device__ float g_r   [M_ROWS * DM];
__device__ float g_xz  [M_ROWS * 2 * DI];
__device__ float g_xc  [M_ROWS * DI];
__device__ float g_proj[M_ROWS * PROJ_N];
__device__ float g_dt  [M_ROWS * DI];
__device__ float g_y   [M_ROWS * DI];

// ---------------- tf32 helpers (family-common PTX, compiles for compute_103) ----
__device__ __forceinline__ uint32_t f2tf(float f) {
    uint32_t r;
    asm("cvt.rna.tf32.f32 %0, %1;" : "=r"(r) : "f"(f));
    return r;
}

__device__ __forceinline__ void mma_16n8k8(float* d, const uint32_t* a, const uint32_t* b) {
    asm volatile(
        "mma.sync.aligned.m16n8k8.row.col.f32.tf32.tf32.f32 "
        "{%0,%1,%2,%3}, {%4,%5,%6,%7}, {%8,%9}, {%0,%1,%2,%3};"
        : "+f"(d[0]), "+f"(d[1]), "+f"(d[2]), "+f"(d[3])
        : "r"(a[0]), "r"(a[1]), "r"(a[2]), "r"(a[3]), "r"(b[0]), "r"(b[1]));
}

// ======== tf32 mma.sync GEMM NT: C[M,N] (+)= A[M,K] * B[N,K]^T ========
// Block tile 128x128, BK=32, 256 threads (8 warps, warp tile 32x64).
// M % 128 == 0, K % 32 == 0; N arbitrary (guarded).
// smem: double-buffered A,B tiles [128][36] (pad for conflict-free frag reads).
#define TSTRIDE 36
#define TILE_F  (128 * TSTRIDE)           // floats per tile
#define MMA_SMEM (2 * 2 * TILE_F * 4)     // bytes = 73728

template <bool ADD>
__global__ void __launch_bounds__(256)
tf32_gemm_nt(const float* __restrict__ A, const float* __restrict__ B,
             float* __restrict__ C, int N, int Kdim, int lda, int ldb, int ldc) {
    extern __shared__ uint32_t smem[];
    // [buf][A|B][TILE_F]
    const int tid = threadIdx.x;
    const int wid = tid >> 5;
    const int lane = tid & 31;
    const int g = lane >> 2;     // group (row within frag)
    const int t = lane & 3;      // thread-in-group (col within frag)
    const int wm = wid & 3;      // warp M index (4)
    const int wn = wid >> 2;     // warp N index (2)
    const int bm = blockIdx.x * 128;
    const int bn = blockIdx.y * 128;

    float acc[2][8][4];
    #pragma unroll
    for (int i = 0; i < 2; i++)
        #pragma unroll
        for (int j = 0; j < 8; j++)
            #pragma unroll
            for (int k = 0; k < 4; k++) acc[i][j][k] = 0.f;

    const int NC = Kdim / 32;

    // per-thread load coordinates: 4 float4 per matrix per chunk
    // i = tid + j*256 ; row = i>>3 ; col4 = (i&7)*4
    float4 pa[4], pb[4];
    {
        #pragma unroll
        for (int j = 0; j < 4; j++) {
            int i = tid + j * 256;
            int r = i >> 3, c4 = (i & 7) * 4;
            pa[j] = *(const float4*)(A + (size_t)(bm + r) * lda + c4);
            pb[j] = (bn + r < N)
                  ? *(const float4*)(B + (size_t)(bn + r) * ldb + c4)
                  : make_float4(0.f, 0.f, 0.f, 0.f);
        }
    }

    for (int c = 0; c < NC; c++) {
        const int buf = c & 1;
        uint32_t* As = smem + buf * (2 * TILE_F);
        uint32_t* Bs = As + TILE_F;

        // store prefetched chunk (with rna tf32 conversion)
        #pragma unroll
        for (int j = 0; j < 4; j++) {
            int i = tid + j * 256;
            int r = i >> 3, c4 = (i & 7) * 4;
            *(uint4*)&As[r * TSTRIDE + c4] =
                make_uint4(f2tf(pa[j].x), f2tf(pa[j].y), f2tf(pa[j].z), f2tf(pa[j].w));
            *(uint4*)&Bs[r * TSTRIDE + c4] =
                make_uint4(f2tf(pb[j].x), f2tf(pb[j].y), f2tf(pb[j].z), f2tf(pb[j].w));
        }
        __syncthreads();

        // prefetch next chunk
        if (c + 1 < NC) {
            int k0 = (c + 1) * 32;
            #pragma unroll
            for (int j = 0; j < 4; j++) {
                int i = tid + j * 256;
                int r = i >> 3, c4 = (i & 7) * 4;
                pa[j] = *(const float4*)(A + (size_t)(bm + r) * lda + k0 + c4);
                pb[j] = (bn + r < N)
                      ? *(const float4*)(B + (size_t)(bn + r) * ldb + k0 + c4)
                      : make_float4(0.f, 0.f, 0.f, 0.f);
            }
        }

        // compute 4 k8-steps
        #pragma unroll
        for (int s = 0; s < 4; s++) {
            const int kb = s * 8;
            uint32_t af[2][4];
            #pragma unroll
            for (int fm = 0; fm < 2; fm++) {
                int r0 = wm * 32 + fm * 16 + g;
                af[fm][0] = As[(r0    ) * TSTRIDE + kb + t    ];
                af[fm][1] = As[(r0 + 8) * TSTRIDE + kb + t    ];
                af[fm][2] = As[(r0    ) * TSTRIDE + kb + t + 4];
                af[fm][3] = As[(r0 + 8) * TSTRIDE + kb + t + 4];
            }
            uint32_t bf[8][2];
            #pragma unroll
            for (int fn = 0; fn < 8; fn++) {
                int n0 = wn * 64 + fn * 8 + g;
                bf[fn][0] = Bs[n0 * TSTRIDE + kb + t    ];
                bf[fn][1] = Bs[n0 * TSTRIDE + kb + t + 4];
            }
            #pragma unroll
            for (int fm = 0; fm < 2; fm++)
                #pragma unroll
                for (int fn = 0; fn < 8; fn++)
                    mma_16n8k8(acc[fm][fn], af[fm], bf[fn]);
        }
        __syncthreads();
    }

    // writeback
    #pragma unroll
    for (int fm = 0; fm < 2; fm++) {
        int row0 = bm + wm * 32 + fm * 16 + g;
        #pragma unroll
        for (int fn = 0; fn < 8; fn++) {
            int col = bn + wn * 64 + fn * 8 + t * 2;
            if (col < N) {
                float* p0 = C + (size_t)row0 * ldc + col;
                float* p1 = C + (size_t)(row0 + 8) * ldc + col;
                if (ADD) {
                    p0[0] += acc[fm][fn][0]; p0[1] += acc[fm][fn][1];
                    p1[0] += acc[fm][fn][2]; p1[1] += acc[fm][fn][3];
                } else {
                    p0[0] = acc[fm][fn][0]; p0[1] = acc[fm][fn][1];
                    p1[0] = acc[fm][fn][2]; p1[1] = acc[fm][fn][3];
                }
            }
        }
    }
}

// ---------------- embed gather ----------------
__global__ void embed_kernel(const int* __restrict__ ids, const int* __restrict__ mask,
                             const float* __restrict__ embed, float* __restrict__ h) {
    int i = blockIdx.x * blockDim.x + threadIdx.x;
    if (i >= M_ROWS * DM) return;
    int row = i / DM, d = i % DM;
    float m = (float)mask[row];
    h[i] = embed[(size_t)ids[row] * DM + d] * m;
}

// ---------------- rmsnorm ----------------
__global__ void rmsnorm_kernel(const float* __restrict__ x, const float* __restrict__ w,
                               float* __restrict__ out) {
    int row = blockIdx.x;
    const float* xr = x + (size_t)row * DM;
    float s = 0.f;
    for (int d = threadIdx.x; d < DM; d += 256) { float v = xr[d]; s += v * v; }
    #pragma unroll
    for (int o = 16; o; o >>= 1) s += __shfl_xor_sync(0xffffffffu, s, o);
    __shared__ float sm[8];
    __shared__ float s_inv;
    if ((threadIdx.x & 31) == 0) sm[threadIdx.x >> 5] = s;
    __syncthreads();
    if (threadIdx.x == 0) {
        float tot = 0.f;
        #pragma unroll
        for (int i = 0; i < 8; i++) tot += sm[i];
        s_inv = rsqrtf(tot / (float)DM + 1e-5f);
    }
    __syncthreads();
    float inv = s_inv;
    for (int d = threadIdx.x; d < DM; d += 256)
        out[(size_t)row * DM + d] = xr[d] * inv * w[d];
}

// ---------------- fp32 SGEMM NT (for dt_proj, K=48) ----------------
template <bool ADD>
__global__ void __launch_bounds__(256)
sgemm_nt(const float* __restrict__ A, const float* __restrict__ B,
         float* __restrict__ C, int M, int N, int Kdim,
         int lda, int ldb, int ldc) {
    __shared__ float As[16][128];
    __shared__ float Bs[16][64 + 4];
    int bm = blockIdx.y * 128;
    int bn = blockIdx.x * 64;
    int tid = threadIdx.x;
    int tx = tid & 15;
    int ty = tid >> 4;
    float acc[8][4];
    #pragma unroll
    for (int i = 0; i < 8; i++)
        #pragma unroll
        for (int j = 0; j < 4; j++) acc[i][j] = 0.f;

    for (int k0 = 0; k0 < Kdim; k0 += 16) {
        #pragma unroll
        for (int it = 0; it < 2; it++) {
            int i = tid + it * 256;
            int r = i >> 2, c4 = (i & 3) * 4;
            float4 v = *(const float4*)(A + (size_t)(bm + r) * lda + k0 + c4);
            As[c4 + 0][r] = v.x; As[c4 + 1][r] = v.y;
            As[c4 + 2][r] = v.z; As[c4 + 3][r] = v.w;
        }
        {
            int r = tid >> 2, c4 = (tid & 3) * 4;
            float4 v = make_float4(0.f, 0.f, 0.f, 0.f);
            if (bn + r < N)
                v = *(const float4*)(B + (size_t)(bn + r) * ldb + k0 + c4);
            Bs[c4 + 0][r] = v.x; Bs[c4 + 1][r] = v.y;
            Bs[c4 + 2][r] = v.z; Bs[c4 + 3][r] = v.w;
        }
        __syncthreads();
        #pragma unroll
        for (int c = 0; c < 16; c++) {
            float ra[8], rb[4];
            #pragma unroll
            for (int i = 0; i < 8; i++) ra[i] = As[c][ty * 8 + i];
            #pragma unroll
            for (int j = 0; j < 4; j++) rb[j] = Bs[c][tx * 4 + j];
            #pragma unroll
            for (int i = 0; i < 8; i++)
                #pragma unroll
                for (int j = 0; j < 4; j++)
                    acc[i][j] += ra[i] * rb[j];
        }
        __syncthreads();
    }

    #pragma unroll
    for (int i = 0; i < 8; i++) {
        int row = bm + ty * 8 + i;
        #pragma unroll
        for (int j = 0; j < 4; j++) {
            int col = bn + tx * 4 + j;
            if (col < N) {
                size_t idx = (size_t)row * ldc + col;
                if (ADD) C[idx] += acc[i][j];
                else     C[idx]  = acc[i][j];
            }
        }
    }
}

// ---------------- depthwise causal conv (K=4) + SiLU ----------------
__global__ void conv_silu_kernel(const float* __restrict__ xz, const float* __restrict__ cw,
                                 const float* __restrict__ cb, float* __restrict__ xc) {
    int i = blockIdx.x * blockDim.x + threadIdx.x;
    if (i >= M_ROWS * DI) return;
    int row = i / DI, d = i % DI;
    int b = row / L_SEQ, l = row % L_SEQ;
    float acc = cb[d];
    #pragma unroll
    for (int k = 0; k < KCONV; k++) {
        int ll = l - (KCONV - 1) + k;
        if (ll >= 0)
            acc += cw[d * KCONV + k] * xz[(size_t)(b * L_SEQ + ll) * (2 * DI) + d];
    }
    xc[i] = acc / (1.f + __expf(-acc));
}

// ---------------- dt bias + softplus ----------------
__global__ void dt_softplus_kernel(float* __restrict__ dt, const float* __restrict__ dtb) {
    int i = blockIdx.x * blockDim.x + threadIdx.x;
    if (i >= M_ROWS * DI) return;
    int d = i % DI;
    float v = dt[i] + dtb[d];
    dt[i] = (v > 20.f) ? v : log1pf(__expf(v));
}

// ---------------- SSM scan ----------------
__global__ void scan_kernel(const float* __restrict__ dt, const float* __restrict__ xc,
                            const float* __restrict__ proj, const float* __restrict__ xz,
                            const float* __restrict__ A_log, const float* __restrict__ Dp,
                            float* __restrict__ y) {
    int gid = (blockIdx.x * blockDim.x + threadIdx.x) >> 4;
    int n = threadIdx.x & 15;
    if (gid >= BATCH * DI) return;
    int b = gid / DI, d = gid % DI;
    float A = -__expf(A_log[d * NSTATE + n]);
    float Dval = Dp[d];
    float h = 0.f;
    for (int l = 0; l < L_SEQ; l++) {
        size_t row = (size_t)b * L_SEQ + l;
        float dtv = dt[row * DI + d];
        float xv  = xc[row * DI + d];
        float Bv  = proj[row * PROJ_N + RRANK + n];
        float Cv  = proj[row * PROJ_N + RRANK + NSTATE + n];
        h = __expf(dtv * A) * h + dtv * Bv * xv;
        float p = h * Cv;
        p += __shfl_xor_sync(0xffffffffu, p, 1);
        p += __shfl_xor_sync(0xffffffffu, p, 2);
        p += __shfl_xor_sync(0xffffffffu, p, 4);
        p += __shfl_xor_sync(0xffffffffu, p, 8);
        if (n == 0) {
            float zv = xz[row * (2 * DI) + DI + d];
            float yv = p + Dval * xv;
            y[row * DI + d] = yv * (zv / (1.f + __expf(-zv)));
        }
    }
}

// ---------------- host orchestration ----------------
extern "C" void kernel_launch(void* const* d_in, const int* in_sizes, int n_in,
                              void* d_out, int out_size) {
    const int*   q_ids   = (const int*)d_in[0];
    const int*   q_mask  = (const int*)d_in[1];
    const float* embed   = (const float*)d_in[4];
    const float* in_w    = (const float*)d_in[5];
    const float* conv_w  = (const float*)d_in[6];
    const float* conv_b  = (const float*)d_in[7];
    const float* x_w     = (const float*)d_in[8];
    const float* dt_w    = (const float*)d_in[9];
    const float* dt_b    = (const float*)d_in[10];
    const float* A_log   = (const float*)d_in[11];
    const float* Dp      = (const float*)d_in[12];
    const float* out_w   = (const float*)d_in[13];
    const float* norm_w  = (const float*)d_in[14];
    const float* fnorm_w = (const float*)d_in[15];
    float* out = (float*)d_out;

    static bool attr_done = false;
    if (!attr_done) {
        cudaFuncSetAttribute(tf32_gemm_nt<false>,
                             cudaFuncAttributeMaxDynamicSharedMemorySize, MMA_SMEM);
        cudaFuncSetAttribute(tf32_gemm_nt<true>,
                             cudaFuncAttributeMaxDynamicSharedMemorySize, MMA_SMEM);
        attr_done = true;
    }

    float *h, *r, *xz, *xc, *proj, *dt, *y;
    cudaGetSymbolAddress((void**)&h,    g_h);
    cudaGetSymbolAddress((void**)&r,    g_r);
    cudaGetSymbolAddress((void**)&xz,   g_xz);
    cudaGetSymbolAddress((void**)&xc,   g_xc);
    cudaGetSymbolAddress((void**)&proj, g_proj);
    cudaGetSymbolAddress((void**)&dt,   g_dt);
    cudaGetSymbolAddress((void**)&y,    g_y);

    embed_kernel<<<(M_ROWS * DM + 255) / 256, 256>>>(q_ids, q_mask, embed, h);

    for (int l = 0; l < NLAYER; l++) {
        const float* in_w_l  = in_w  + (size_t)l * (2 * DI) * DM;
        const float* cw_l    = conv_w + (size_t)l * DI * KCONV;
        const float* cb_l    = conv_b + (size_t)l * DI;
        const float* x_w_l   = x_w   + (size_t)l * PROJ_N * DI;
        const float* dt_w_l  = dt_w  + (size_t)l * DI * RRANK;
        const float* dt_b_l  = dt_b  + (size_t)l * DI;
        const float* A_log_l = A_log + (size_t)l * DI * NSTATE;
        const float* Dp_l    = Dp    + (size_t)l * DI;
        const float* out_w_l = out_w + (size_t)l * DM * DI;
        const float* norm_l  = norm_w + (size_t)l * DM;

        rmsnorm_kernel<<<M_ROWS, 256>>>(h, norm_l, r);

        // xz = r @ in_w^T  (1024 x 3072, K=768) — tf32 mma
        tf32_gemm_nt<false><<<dim3(M_ROWS / 128, (2 * DI + 127) / 128), 256, MMA_SMEM>>>(
            r, in_w_l, xz, 2 * DI, DM, DM, DM, 2 * DI);

        conv_silu_kernel<<<(M_ROWS * DI + 255) / 256, 256>>>(xz, cw_l, cb_l, xc);

        // proj = xc @ x_w^T  (1024 x 80, K=1536) — tf32 mma
        tf32_gemm_nt<false><<<dim3(M_ROWS / 128, 1), 256, MMA_SMEM>>>(
            xc, x_w_l, proj, PROJ_N, DI, DI, DI, PROJ_N);

        // dt = proj[:, :48] @ dt_w^T  (1024 x 1536, K=48) — fp32
        sgemm_nt<false><<<dim3((DI + 63) / 64, M_ROWS / 128), 256>>>(
            proj, dt_w_l, dt, M_ROWS, DI, RRANK, PROJ_N, RRANK, DI);

        dt_softplus_kernel<<<(M_ROWS * DI + 255) / 256, 256>>>(dt, dt_b_l);

        scan_kernel<<<(BATCH * DI * 16 + 255) / 256, 256>>>(
            dt, xc, proj, xz, A_log_l, Dp_l, y);

        // h += y @ out_w^T  (1024 x 768, K=1536) — tf32 mma
        tf32_gemm_nt<true><<<dim3(M_ROWS / 128, DM / 128), 256, MMA_SMEM>>>(
            y, out_w_l, h, DM, DI, DI, DI, DM);
    }

    rmsnorm_kernel<<<M_ROWS, 256>>>(h, fnorm_w, r);

    // logits = r @ embed^T  (1024 x 50280, K=768) — tf32 mma
    tf32_gemm_nt<false><<<dim3(M_ROWS / 128, (VOCAB + 127) / 128), 256, MMA_SMEM>>>(
        r, embed, out, VOCAB, DM, DM, DM, VOCAB);
}

// round 4
// speedup vs baseline: 2.7518x; 1.4419x over previous
#include <cuda_runtime.h>
#include <math.h>
#include <stdint.h>

// ---------------- problem constants ----------------
#define BATCH   2
#define L_SEQ   512
#define DM      768
#define DI      1536
#define NSTATE  16
#define RRANK   48
#define KCONV   4
#define NLAYER  4
#define VOCAB   50280
#define M_ROWS  (BATCH * L_SEQ)        // 1024
#define PROJ_N  (RRANK + 2 * NSTATE)   // 80

// ---------------- scratch (device globals) ----------------
__device__ float g_h   [M_ROWS * DM];
__device__ float g_r   [M_ROWS * DM];
__device__ float g_xz  [M_ROWS * 2 * DI];
__device__ float g_xc  [M_ROWS * DI];
__device__ float g_proj[M_ROWS * PROJ_N];
__device__ float g_dt  [M_ROWS * DI];
__device__ float g_y   [M_ROWS * DI];

// ---------------- PTX helpers (family-common; compile for compute_103) -------
__device__ __forceinline__ uint32_t f2tf(float f) {
    uint32_t r;
    asm("cvt.rna.tf32.f32 %0, %1;" : "=r"(r) : "f"(f));
    return r;
}
__device__ __forceinline__ uint32_t smem_u32(const void* p) {
    uint32_t a;
    asm("{ .reg .u64 t; cvta.to.shared.u64 t, %1; cvt.u32.u64 %0, t; }"
        : "=r"(a) : "l"(p));
    return a;
}
__device__ __forceinline__ void ldsm4(uint32_t* r, uint32_t addr) {
    asm volatile("ldmatrix.sync.aligned.m8n8.x4.shared.b16 {%0,%1,%2,%3}, [%4];"
        : "=r"(r[0]), "=r"(r[1]), "=r"(r[2]), "=r"(r[3]) : "r"(addr));
}
__device__ __forceinline__ void mma_16n8k8(float* d, const uint32_t* a, const uint32_t* b) {
    asm volatile(
        "mma.sync.aligned.m16n8k8.row.col.f32.tf32.tf32.f32 "
        "{%0,%1,%2,%3}, {%4,%5,%6,%7}, {%8,%9}, {%0,%1,%2,%3};"
        : "+f"(d[0]), "+f"(d[1]), "+f"(d[2]), "+f"(d[3])
        : "r"(a[0]), "r"(a[1]), "r"(a[2]), "r"(a[3]), "r"(b[0]), "r"(b[1]));
}

// ======== tf32 mma.sync GEMM NT: C[M,N] (op)= A[M,K] * B[N,K]^T ========
// Block tile 128x128, BK=32, 256 threads (8 warps, 4M x 2N, warp tile 32x64).
// M % 128 == 0, Klen % 32 == 0; N arbitrary (guarded).
// blockIdx.z = K-split index; each CTA processes Klen of K starting z*Klen.
// MODE: 0 = store, 1 = add, 2 = atomicAdd (for split-K).
#define TSTRIDE 36
#define TILE_F  (128 * TSTRIDE)           // u32 per tile
#define MMA_SMEM (2 * 2 * TILE_F * 4)     // bytes = 73728

template <int MODE>
__global__ void __launch_bounds__(256)
tf32_gemm_nt(const float* __restrict__ A, const float* __restrict__ B,
             float* __restrict__ C, int N, int Klen, int lda, int ldb, int ldc) {
    extern __shared__ uint32_t smem[];
    const int tid = threadIdx.x;
    const int wid = tid >> 5;
    const int lane = tid & 31;
    const int g = lane >> 2;
    const int t = lane & 3;
    const int wm = wid & 3;      // warp M index (4)
    const int wn = wid >> 2;     // warp N index (2)
    const int bm = blockIdx.x * 128;
    const int bn = blockIdx.y * 128;
    const int kbase = blockIdx.z * Klen;

    const uint32_t sbase = smem_u32(smem);

    // per-lane ldmatrix source offsets (bytes from tile base)
    const int j8  = lane & 7;
    const int sel = lane >> 3;
    uint32_t aoff[2], boff[4];
    #pragma unroll
    for (int fm = 0; fm < 2; fm++) {
        int row = wm * 32 + fm * 16 + j8 + ((sel & 1) << 3);
        aoff[fm] = (uint32_t)(row * (TSTRIDE * 4) + ((sel & 2) ? 16 : 0));
    }
    #pragma unroll
    for (int p = 0; p < 4; p++) {
        int row = wn * 64 + p * 16 + j8 + ((sel & 2) ? 8 : 0);
        boff[p] = (uint32_t)(row * (TSTRIDE * 4) + ((sel & 1) ? 16 : 0));
    }

    float acc[2][8][4];
    #pragma unroll
    for (int i = 0; i < 2; i++)
        #pragma unroll
        for (int jj = 0; jj < 8; jj++)
            #pragma unroll
            for (int k = 0; k < 4; k++) acc[i][jj][k] = 0.f;

    const int NC = Klen / 32;

    // prefetch chunk 0 into registers
    float4 pa[4], pb[4];
    #pragma unroll
    for (int jj = 0; jj < 4; jj++) {
        int i = tid + jj * 256;
        int r = i >> 3, c4 = (i & 7) * 4;
        pa[jj] = *(const float4*)(A + (size_t)(bm + r) * lda + kbase + c4);
        pb[jj] = (bn + r < N)
              ? *(const float4*)(B + (size_t)(bn + r) * ldb + kbase + c4)
              : make_float4(0.f, 0.f, 0.f, 0.f);
    }

    for (int c = 0; c < NC; c++) {
        const int buf = c & 1;
        uint32_t* As = smem + buf * (2 * TILE_F);
        uint32_t* Bs = As + TILE_F;
        const uint32_t abase = sbase + (uint32_t)buf * (2 * TILE_F * 4);
        const uint32_t bbase = abase + TILE_F * 4;

        // store prefetched chunk (rna tf32 conversion fused)
        #pragma unroll
        for (int jj = 0; jj < 4; jj++) {
            int i = tid + jj * 256;
            int r = i >> 3, c4 = (i & 7) * 4;
            *(uint4*)&As[r * TSTRIDE + c4] =
                make_uint4(f2tf(pa[jj].x), f2tf(pa[jj].y), f2tf(pa[jj].z), f2tf(pa[jj].w));
            *(uint4*)&Bs[r * TSTRIDE + c4] =
                make_uint4(f2tf(pb[jj].x), f2tf(pb[jj].y), f2tf(pb[jj].z), f2tf(pb[jj].w));
        }
        __syncthreads();

        // prefetch next chunk
        if (c + 1 < NC) {
            int k0 = kbase + (c + 1) * 32;
            #pragma unroll
            for (int jj = 0; jj < 4; jj++) {
                int i = tid + jj * 256;
                int r = i >> 3, c4 = (i & 7) * 4;
                pa[jj] = *(const float4*)(A + (size_t)(bm + r) * lda + k0 + c4);
                pb[jj] = (bn + r < N)
                      ? *(const float4*)(B + (size_t)(bn + r) * ldb + k0 + c4)
                      : make_float4(0.f, 0.f, 0.f, 0.f);
            }
        }

        // compute: 4 k8-steps via ldmatrix fragments
        #pragma unroll
        for (int s = 0; s < 4; s++) {
            const uint32_t soff = (uint32_t)(s * 32);
            uint32_t af0[4], af1[4];
            ldsm4(af0, abase + aoff[0] + soff);
            ldsm4(af1, abase + aoff[1] + soff);
            #pragma unroll
            for (int p = 0; p < 4; p++) {
                uint32_t bfr[4];
                ldsm4(bfr, bbase + boff[p] + soff);
                mma_16n8k8(acc[0][2 * p],     af0, bfr);
                mma_16n8k8(acc[0][2 * p + 1], af0, bfr + 2);
                mma_16n8k8(acc[1][2 * p],     af1, bfr);
                mma_16n8k8(acc[1][2 * p + 1], af1, bfr + 2);
            }
        }
        __syncthreads();
    }

    // writeback
    #pragma unroll
    for (int fm = 0; fm < 2; fm++) {
        int row0 = bm + wm * 32 + fm * 16 + g;
        #pragma unroll
        for (int fn = 0; fn < 8; fn++) {
            int col = bn + wn * 64 + fn * 8 + t * 2;
            if (col < N) {
                float* p0 = C + (size_t)row0 * ldc + col;
                float* p1 = C + (size_t)(row0 + 8) * ldc + col;
                if (MODE == 0) {
                    p0[0] = acc[fm][fn][0]; p0[1] = acc[fm][fn][1];
                    p1[0] = acc[fm][fn][2]; p1[1] = acc[fm][fn][3];
                } else if (MODE == 1) {
                    p0[0] += acc[fm][fn][0]; p0[1] += acc[fm][fn][1];
                    p1[0] += acc[fm][fn][2]; p1[1] += acc[fm][fn][3];
                } else {
                    atomicAdd(p0,     acc[fm][fn][0]);
                    atomicAdd(p0 + 1, acc[fm][fn][1]);
                    atomicAdd(p1,     acc[fm][fn][2]);
                    atomicAdd(p1 + 1, acc[fm][fn][3]);
                }
            }
        }
    }
}

// ---------------- zero fill ----------------
__global__ void zero_kernel(float* __restrict__ p, int n) {
    int i = blockIdx.x * blockDim.x + threadIdx.x;
    if (i < n) p[i] = 0.f;
}

// ---------------- embed gather ----------------
__global__ void embed_kernel(const int* __restrict__ ids, const int* __restrict__ mask,
                             const float* __restrict__ embed, float* __restrict__ h) {
    int i = blockIdx.x * blockDim.x + threadIdx.x;
    if (i >= M_ROWS * DM) return;
    int row = i / DM, d = i % DM;
    float m = (float)mask[row];
    h[i] = embed[(size_t)ids[row] * DM + d] * m;
}

// ---------------- rmsnorm ----------------
__global__ void rmsnorm_kernel(const float* __restrict__ x, const float* __restrict__ w,
                               float* __restrict__ out) {
    int row = blockIdx.x;
    const float* xr = x + (size_t)row * DM;
    float s = 0.f;
    for (int d = threadIdx.x; d < DM; d += 256) { float v = xr[d]; s += v * v; }
    #pragma unroll
    for (int o = 16; o; o >>= 1) s += __shfl_xor_sync(0xffffffffu, s, o);
    __shared__ float sm[8];
    __shared__ float s_inv;
    if ((threadIdx.x & 31) == 0) sm[threadIdx.x >> 5] = s;
    __syncthreads();
    if (threadIdx.x == 0) {
        float tot = 0.f;
        #pragma unroll
        for (int i = 0; i < 8; i++) tot += sm[i];
        s_inv = rsqrtf(tot / (float)DM + 1e-5f);
    }
    __syncthreads();
    float inv = s_inv;
    for (int d = threadIdx.x; d < DM; d += 256)
        out[(size_t)row * DM + d] = xr[d] * inv * w[d];
}

// ---------------- fp32 SGEMM NT (for dt_proj, K=48) ----------------
__global__ void __launch_bounds__(256)
sgemm_nt(const float* __restrict__ A, const float* __restrict__ B,
         float* __restrict__ C, int M, int N, int Kdim,
         int lda, int ldb, int ldc) {
    __shared__ float As[16][128];
    __shared__ float Bs[16][64 + 4];
    int bm = blockIdx.y * 128;
    int bn = blockIdx.x * 64;
    int tid = threadIdx.x;
    int tx = tid & 15;
    int ty = tid >> 4;
    float acc[8][4];
    #pragma unroll
    for (int i = 0; i < 8; i++)
        #pragma unroll
        for (int j = 0; j < 4; j++) acc[i][j] = 0.f;

    for (int k0 = 0; k0 < Kdim; k0 += 16) {
        #pragma unroll
        for (int it = 0; it < 2; it++) {
            int i = tid + it * 256;
            int r = i >> 2, c4 = (i & 3) * 4;
            float4 v = *(const float4*)(A + (size_t)(bm + r) * lda + k0 + c4);
            As[c4 + 0][r] = v.x; As[c4 + 1][r] = v.y;
            As[c4 + 2][r] = v.z; As[c4 + 3][r] = v.w;
        }
        {
            int r = tid >> 2, c4 = (tid & 3) * 4;
            float4 v = make_float4(0.f, 0.f, 0.f, 0.f);
            if (bn + r < N)
                v = *(const float4*)(B + (size_t)(bn + r) * ldb + k0 + c4);
            Bs[c4 + 0][r] = v.x; Bs[c4 + 1][r] = v.y;
            Bs[c4 + 2][r] = v.z; Bs[c4 + 3][r] = v.w;
        }
        __syncthreads();
        #pragma unroll
        for (int c = 0; c < 16; c++) {
            float ra[8], rb[4];
            #pragma unroll
            for (int i = 0; i < 8; i++) ra[i] = As[c][ty * 8 + i];
            #pragma unroll
            for (int j = 0; j < 4; j++) rb[j] = Bs[c][tx * 4 + j];
            #pragma unroll
            for (int i = 0; i < 8; i++)
                #pragma unroll
                for (int j = 0; j < 4; j++)
                    acc[i][j] += ra[i] * rb[j];
        }
        __syncthreads();
    }

    #pragma unroll
    for (int i = 0; i < 8; i++) {
        int row = bm + ty * 8 + i;
        #pragma unroll
        for (int j = 0; j < 4; j++) {
            int col = bn + tx * 4 + j;
            if (col < N) C[(size_t)row * ldc + col] = acc[i][j];
        }
    }
}

// ---------------- depthwise causal conv (K=4) + SiLU ----------------
__global__ void conv_silu_kernel(const float* __restrict__ xz, const float* __restrict__ cw,
                                 const float* __restrict__ cb, float* __restrict__ xc) {
    int i = blockIdx.x * blockDim.x + threadIdx.x;
    if (i >= M_ROWS * DI) return;
    int row = i / DI, d = i % DI;
    int b = row / L_SEQ, l = row % L_SEQ;
    float acc = cb[d];
    #pragma unroll
    for (int k = 0; k < KCONV; k++) {
        int ll = l - (KCONV - 1) + k;
        if (ll >= 0)
            acc += cw[d * KCONV + k] * xz[(size_t)(b * L_SEQ + ll) * (2 * DI) + d];
    }
    xc[i] = acc / (1.f + __expf(-acc));
}

// ---------------- dt bias + softplus ----------------
__global__ void dt_softplus_kernel(float* __restrict__ dt, const float* __restrict__ dtb) {
    int i = blockIdx.x * blockDim.x + threadIdx.x;
    if (i >= M_ROWS * DI) return;
    int d = i % DI;
    float v = dt[i] + dtb[d];
    dt[i] = (v > 20.f) ? v : log1pf(__expf(v));
}

// ---------------- SSM scan (software-pipelined loads) ----------------
__global__ void scan_kernel(const float* __restrict__ dt, const float* __restrict__ xc,
                            const float* __restrict__ proj, const float* __restrict__ xz,
                            const float* __restrict__ A_log, const float* __restrict__ Dp,
                            float* __restrict__ y) {
    int gid = (blockIdx.x * blockDim.x + threadIdx.x) >> 4;
    int n = threadIdx.x & 15;
    if (gid >= BATCH * DI) return;
    int b = gid / DI, d = gid % DI;
    float A = -__expf(A_log[d * NSTATE + n]);
    float Dval = Dp[d];
    float h = 0.f;

    size_t row0 = (size_t)b * L_SEQ;
    float dtv = dt[row0 * DI + d];
    float xv  = xc[row0 * DI + d];
    float Bv  = proj[row0 * PROJ_N + RRANK + n];
    float Cv  = proj[row0 * PROJ_N + RRANK + NSTATE + n];

    for (int l = 0; l < L_SEQ; l++) {
        size_t row = row0 + l;
        float ndt = 0.f, nxv = 0.f, nBv = 0.f, nCv = 0.f;
        if (l + 1 < L_SEQ) {
            size_t rn = row + 1;
            ndt = dt[rn * DI + d];
            nxv = xc[rn * DI + d];
            nBv = proj[rn * PROJ_N + RRANK + n];
            nCv = proj[rn * PROJ_N + RRANK + NSTATE + n];
        }
        h = __expf(dtv * A) * h + dtv * Bv * xv;
        float p = h * Cv;
        p += __shfl_xor_sync(0xffffffffu, p, 1);
        p += __shfl_xor_sync(0xffffffffu, p, 2);
        p += __shfl_xor_sync(0xffffffffu, p, 4);
        p += __shfl_xor_sync(0xffffffffu, p, 8);
        if (n == 0) {
            float zv = xz[row * (2 * DI) + DI + d];
            float yv = p + Dval * xv;
            y[row * DI + d] = yv * (zv / (1.f + __expf(-zv)));
        }
        dtv = ndt; xv = nxv; Bv = nBv; Cv = nCv;
    }
}

// ---------------- host orchestration ----------------
extern "C" void kernel_launch(void* const* d_in, const int* in_sizes, int n_in,
                              void* d_out, int out_size) {
    const int*   q_ids   = (const int*)d_in[0];
    const int*   q_mask  = (const int*)d_in[1];
    const float* embed   = (const float*)d_in[4];
    const float* in_w    = (const float*)d_in[5];
    const float* conv_w  = (const float*)d_in[6];
    const float* conv_b  = (const float*)d_in[7];
    const float* x_w     = (const float*)d_in[8];
    const float* dt_w    = (const float*)d_in[9];
    const float* dt_b    = (const float*)d_in[10];
    const float* A_log   = (const float*)d_in[11];
    const float* Dp      = (const float*)d_in[12];
    const float* out_w   = (const float*)d_in[13];
    const float* norm_w  = (const float*)d_in[14];
    const float* fnorm_w = (const float*)d_in[15];
    float* out = (float*)d_out;

    cudaFuncSetAttribute(tf32_gemm_nt<0>, cudaFuncAttributeMaxDynamicSharedMemorySize, MMA_SMEM);
    cudaFuncSetAttribute(tf32_gemm_nt<2>, cudaFuncAttributeMaxDynamicSharedMemorySize, MMA_SMEM);

    float *h, *r, *xz, *xc, *proj, *dt, *y;
    cudaGetSymbolAddress((void**)&h,    g_h);
    cudaGetSymbolAddress((void**)&r,    g_r);
    cudaGetSymbolAddress((void**)&xz,   g_xz);
    cudaGetSymbolAddress((void**)&xc,   g_xc);
    cudaGetSymbolAddress((void**)&proj, g_proj);
    cudaGetSymbolAddress((void**)&dt,   g_dt);
    cudaGetSymbolAddress((void**)&y,    g_y);

    embed_kernel<<<(M_ROWS * DM + 255) / 256, 256>>>(q_ids, q_mask, embed, h);

    for (int l = 0; l < NLAYER; l++) {
        const float* in_w_l  = in_w  + (size_t)l * (2 * DI) * DM;
        const float* cw_l    = conv_w + (size_t)l * DI * KCONV;
        const float* cb_l    = conv_b + (size_t)l * DI;
        const float* x_w_l   = x_w   + (size_t)l * PROJ_N * DI;
        const float* dt_w_l  = dt_w  + (size_t)l * DI * RRANK;
        const float* dt_b_l  = dt_b  + (size_t)l * DI;
        const float* A_log_l = A_log + (size_t)l * DI * NSTATE;
        const float* Dp_l    = Dp    + (size_t)l * DI;
        const float* out_w_l = out_w + (size_t)l * DM * DI;
        const float* norm_l  = norm_w + (size_t)l * DM;

        rmsnorm_kernel<<<M_ROWS, 256>>>(h, norm_l, r);

        // xz = r @ in_w^T  (1024 x 3072, K=768)
        tf32_gemm_nt<0><<<dim3(M_ROWS / 128, (2 * DI + 127) / 128, 1), 256, MMA_SMEM>>>(
            r, in_w_l, xz, 2 * DI, DM, DM, DM, 2 * DI);

        conv_silu_kernel<<<(M_ROWS * DI + 255) / 256, 256>>>(xz, cw_l, cb_l, xc);

        // proj = xc @ x_w^T  (1024 x 80, K=1536) — split-K x8, atomic
        zero_kernel<<<(M_ROWS * PROJ_N + 255) / 256, 256>>>(proj, M_ROWS * PROJ_N);
        tf32_gemm_nt<2><<<dim3(M_ROWS / 128, 1, 8), 256, MMA_SMEM>>>(
            xc, x_w_l, proj, PROJ_N, DI / 8, DI, DI, PROJ_N);

        // dt = proj[:, :48] @ dt_w^T  (1024 x 1536, K=48) — fp32
        sgemm_nt<<<dim3((DI + 63) / 64, M_ROWS / 128), 256>>>(
            proj, dt_w_l, dt, M_ROWS, DI, RRANK, PROJ_N, RRANK, DI);

        dt_softplus_kernel<<<(M_ROWS * DI + 255) / 256, 256>>>(dt, dt_b_l);

        scan_kernel<<<(BATCH * DI * 16 + 255) / 256, 256>>>(
            dt, xc, proj, xz, A_log_l, Dp_l, y);

        // h += y @ out_w^T  (1024 x 768, K=1536) — split-K x4, atomic into residual
        tf32_gemm_nt<2><<<dim3(M_ROWS / 128, DM / 128, 4), 256, MMA_SMEM>>>(
            y, out_w_l, h, DM, DI / 4, DI, DI, DM);
    }

    rmsnorm_kernel<<<M_ROWS, 256>>>(h, fnorm_w, r);

    // logits = r @ embed^T  (1024 x 50280, K=768)
    tf32_gemm_nt<0><<<dim3(M_ROWS / 128, (VOCAB + 127) / 128, 1), 256, MMA_SMEM>>>(
        r, embed, out, VOCAB, DM, DM, DM, VOCAB);
}

// round 5
// speedup vs baseline: 2.8223x; 1.0256x over previous
#include <cuda_runtime.h>
#include <math.h>
#include <stdint.h>

// ---------------- problem constants ----------------
#define BATCH   2
#define L_SEQ   512
#define DM      768
#define DI      1536
#define NSTATE  16
#define RRANK   48
#define KCONV   4
#define NLAYER  4
#define VOCAB   50280
#define M_ROWS  (BATCH * L_SEQ)        // 1024
#define PROJ_N  (RRANK + 2 * NSTATE)   // 80

// ---------------- scratch (device globals) ----------------
__device__ float g_h   [M_ROWS * DM];
__device__ float g_r   [M_ROWS * DM];
__device__ float g_xz  [M_ROWS * 2 * DI];
__device__ float g_xc  [M_ROWS * DI];
__device__ float g_proj[M_ROWS * PROJ_N];
__device__ float g_dt  [M_ROWS * DI];
__device__ float g_y   [M_ROWS * DI];

// ---------------- PTX helpers (family-common; compile for compute_103) -------
__device__ __forceinline__ uint32_t f2tf(float f) {
    uint32_t r;
    asm("cvt.rna.tf32.f32 %0, %1;" : "=r"(r) : "f"(f));
    return r;
}
__device__ __forceinline__ float round_tf32(float f) {
    return __uint_as_float(f2tf(f));
}
__device__ __forceinline__ uint32_t smem_u32(const void* p) {
    uint32_t a;
    asm("{ .reg .u64 t; cvta.to.shared.u64 t, %1; cvt.u32.u64 %0, t; }"
        : "=r"(a) : "l"(p));
    return a;
}
__device__ __forceinline__ void ldsm4(uint32_t* r, uint32_t addr) {
    asm volatile("ldmatrix.sync.aligned.m8n8.x4.shared.b16 {%0,%1,%2,%3}, [%4];"
        : "=r"(r[0]), "=r"(r[1]), "=r"(r[2]), "=r"(r[3]) : "r"(addr));
}
__device__ __forceinline__ void mma_16n8k8(float* d, const uint32_t* a, const uint32_t* b) {
    asm volatile(
        "mma.sync.aligned.m16n8k8.row.col.f32.tf32.tf32.f32 "
        "{%0,%1,%2,%3}, {%4,%5,%6,%7}, {%8,%9}, {%0,%1,%2,%3};"
        : "+f"(d[0]), "+f"(d[1]), "+f"(d[2]), "+f"(d[3])
        : "r"(a[0]), "r"(a[1]), "r"(a[2]), "r"(a[3]), "r"(b[0]), "r"(b[1]));
}
#define CP_ASYNC16(dst, src) \
    asm volatile("cp.async.cg.shared.global [%0], [%1], 16;" :: "r"(dst), "l"(src))
#define CP_COMMIT() asm volatile("cp.async.commit_group;" ::: "memory")
#define CP_WAIT1()  asm volatile("cp.async.wait_group 1;" ::: "memory")

// ======== tf32 mma.sync GEMM NT: C[M,N] (op)= A[M,K] * B[N,K]^T ========
// Block tile 128x128, BK=32, 256 threads (8 warps, 4M x 2N, warp tile 32x64).
// 3-stage cp.async pipeline. M % 128 == 0, Klen % 32 == 0, Klen/32 >= 2.
// A is expected pre-rounded to tf32 (rna); B is raw fp32 (HW truncates).
// blockIdx.z = K-split index. MODE: 0 = store, 1 = add, 2 = atomicAdd.
#define TSTRIDE 36
#define TILE_F  (128 * TSTRIDE)           // u32 per tile (4608)
#define NSTAGE  3
#define STAGE_B (2 * TILE_F * 4)          // bytes per stage (36864)
#define MMA_SMEM (NSTAGE * STAGE_B)       // 110592

template <int MODE>
__global__ void __launch_bounds__(256)
tf32_gemm_nt(const float* __restrict__ A, const float* __restrict__ B,
             float* __restrict__ C, int N, int Klen, int lda, int ldb, int ldc) {
    extern __shared__ uint32_t smem[];
    const int tid = threadIdx.x;
    const int wid = tid >> 5;
    const int lane = tid & 31;
    const int g = lane >> 2;
    const int t = lane & 3;
    const int wm = wid & 3;      // warp M index (4)
    const int wn = wid >> 2;     // warp N index (2)
    const int bm = blockIdx.x * 128;
    const int bn = blockIdx.y * 128;
    const int kbase = blockIdx.z * Klen;

    const uint32_t sbase = smem_u32(smem);

    // per-lane ldmatrix source offsets (bytes from tile base)
    const int j8  = lane & 7;
    const int sel = lane >> 3;
    uint32_t aoff[2], boff[4];
    #pragma unroll
    for (int fm = 0; fm < 2; fm++) {
        int row = wm * 32 + fm * 16 + j8 + ((sel & 1) << 3);
        aoff[fm] = (uint32_t)(row * (TSTRIDE * 4) + ((sel & 2) ? 16 : 0));
    }
    #pragma unroll
    for (int p = 0; p < 4; p++) {
        int row = wn * 64 + p * 16 + j8 + ((sel & 2) ? 8 : 0);
        boff[p] = (uint32_t)(row * (TSTRIDE * 4) + ((sel & 1) ? 16 : 0));
    }

    // per-thread copy descriptors: 4 x 16B per matrix per chunk
    const char* gA[4];
    const char* gB[4];
    uint32_t dA[4], dB[4];
    #pragma unroll
    for (int j = 0; j < 4; j++) {
        int i = tid + j * 256;
        int r = i >> 3, c4 = (i & 7) * 4;
        gA[j] = (const char*)(A + (size_t)(bm + r) * lda + kbase + c4);
        int brow = bn + r; if (brow >= N) brow = N - 1;   // clamp (cols masked later)
        gB[j] = (const char*)(B + (size_t)brow * ldb + kbase + c4);
        dA[j] = (uint32_t)((r * TSTRIDE + c4) * 4);
        dB[j] = dA[j] + TILE_F * 4;
    }

    float acc[2][8][4];
    #pragma unroll
    for (int i = 0; i < 2; i++)
        #pragma unroll
        for (int jj = 0; jj < 8; jj++)
            #pragma unroll
            for (int k = 0; k < 4; k++) acc[i][jj][k] = 0.f;

    const int NC = Klen / 32;

    // prologue: stage chunks 0 .. NSTAGE-2
    #pragma unroll
    for (int s = 0; s < NSTAGE - 1; s++) {
        if (s < NC) {
            uint32_t sb = sbase + (uint32_t)s * STAGE_B;
            size_t off = (size_t)s * 128;
            #pragma unroll
            for (int j = 0; j < 4; j++) {
                CP_ASYNC16(sb + dA[j], gA[j] + off);
                CP_ASYNC16(sb + dB[j], gB[j] + off);
            }
        }
        CP_COMMIT();
    }

    int cs = 0;  // stage of current chunk
    for (int c = 0; c < NC; c++) {
        CP_WAIT1();
        __syncthreads();

        // issue chunk c+NSTAGE-1 into the stage just freed
        int nchunk = c + NSTAGE - 1;
        int is_ = cs + NSTAGE - 1; if (is_ >= NSTAGE) is_ -= NSTAGE;
        if (nchunk < NC) {
            uint32_t sb = sbase + (uint32_t)is_ * STAGE_B;
            size_t off = (size_t)nchunk * 128;
            #pragma unroll
            for (int j = 0; j < 4; j++) {
                CP_ASYNC16(sb + dA[j], gA[j] + off);
                CP_ASYNC16(sb + dB[j], gB[j] + off);
            }
        }
        CP_COMMIT();

        // compute chunk c from stage cs
        const uint32_t abase = sbase + (uint32_t)cs * STAGE_B;
        const uint32_t bbase = abase + TILE_F * 4;
        #pragma unroll
        for (int s = 0; s < 4; s++) {
            const uint32_t soff = (uint32_t)(s * 32);
            uint32_t af0[4], af1[4];
            ldsm4(af0, abase + aoff[0] + soff);
            ldsm4(af1, abase + aoff[1] + soff);
            #pragma unroll
            for (int p = 0; p < 4; p++) {
                uint32_t bfr[4];
                ldsm4(bfr, bbase + boff[p] + soff);
                mma_16n8k8(acc[0][2 * p],     af0, bfr);
                mma_16n8k8(acc[0][2 * p + 1], af0, bfr + 2);
                mma_16n8k8(acc[1][2 * p],     af1, bfr);
                mma_16n8k8(acc[1][2 * p + 1], af1, bfr + 2);
            }
        }
        cs++; if (cs == NSTAGE) cs = 0;
    }

    // writeback
    #pragma unroll
    for (int fm = 0; fm < 2; fm++) {
        int row0 = bm + wm * 32 + fm * 16 + g;
        #pragma unroll
        for (int fn = 0; fn < 8; fn++) {
            int col = bn + wn * 64 + fn * 8 + t * 2;
            if (col < N) {
                float* p0 = C + (size_t)row0 * ldc + col;
                float* p1 = C + (size_t)(row0 + 8) * ldc + col;
                if (MODE == 0) {
                    p0[0] = acc[fm][fn][0]; p0[1] = acc[fm][fn][1];
                    p1[0] = acc[fm][fn][2]; p1[1] = acc[fm][fn][3];
                } else if (MODE == 1) {
                    p0[0] += acc[fm][fn][0]; p0[1] += acc[fm][fn][1];
                    p1[0] += acc[fm][fn][2]; p1[1] += acc[fm][fn][3];
                } else {
                    atomicAdd(p0,     acc[fm][fn][0]);
                    atomicAdd(p0 + 1, acc[fm][fn][1]);
                    atomicAdd(p1,     acc[fm][fn][2]);
                    atomicAdd(p1 + 1, acc[fm][fn][3]);
                }
            }
        }
    }
}

// ---------------- zero fill ----------------
__global__ void zero_kernel(float* __restrict__ p, int n) {
    int i = blockIdx.x * blockDim.x + threadIdx.x;
    if (i < n) p[i] = 0.f;
}

// ---------------- embed gather ----------------
__global__ void embed_kernel(const int* __restrict__ ids, const int* __restrict__ mask,
                             const float* __restrict__ embed, float* __restrict__ h) {
    int i = blockIdx.x * blockDim.x + threadIdx.x;
    if (i >= M_ROWS * DM) return;
    int row = i / DM, d = i % DM;
    float m = (float)mask[row];
    h[i] = embed[(size_t)ids[row] * DM + d] * m;
}

// ---------------- rmsnorm (emits tf32-rounded output) ----------------
__global__ void rmsnorm_kernel(const float* __restrict__ x, const float* __restrict__ w,
                               float* __restrict__ out) {
    int row = blockIdx.x;
    const float* xr = x + (size_t)row * DM;
    float s = 0.f;
    for (int d = threadIdx.x; d < DM; d += 256) { float v = xr[d]; s += v * v; }
    #pragma unroll
    for (int o = 16; o; o >>= 1) s += __shfl_xor_sync(0xffffffffu, s, o);
    __shared__ float sm[8];
    __shared__ float s_inv;
    if ((threadIdx.x & 31) == 0) sm[threadIdx.x >> 5] = s;
    __syncthreads();
    if (threadIdx.x == 0) {
        float tot = 0.f;
        #pragma unroll
        for (int i = 0; i < 8; i++) tot += sm[i];
        s_inv = rsqrtf(tot / (float)DM + 1e-5f);
    }
    __syncthreads();
    float inv = s_inv;
    for (int d = threadIdx.x; d < DM; d += 256)
        out[(size_t)row * DM + d] = round_tf32(xr[d] * inv * w[d]);
}

// ---------------- fp32 SGEMM NT + fused bias/softplus (dt_proj, K=48) --------
__global__ void __launch_bounds__(256)
sgemm_nt_softplus(const float* __restrict__ A, const float* __restrict__ B,
                  float* __restrict__ C, const float* __restrict__ bias,
                  int M, int N, int Kdim, int lda, int ldb, int ldc) {
    __shared__ float As[16][128];
    __shared__ float Bs[16][64 + 4];
    int bm = blockIdx.y * 128;
    int bn = blockIdx.x * 64;
    int tid = threadIdx.x;
    int tx = tid & 15;
    int ty = tid >> 4;
    float acc[8][4];
    #pragma unroll
    for (int i = 0; i < 8; i++)
        #pragma unroll
        for (int j = 0; j < 4; j++) acc[i][j] = 0.f;

    for (int k0 = 0; k0 < Kdim; k0 += 16) {
        #pragma unroll
        for (int it = 0; it < 2; it++) {
            int i = tid + it * 256;
            int r = i >> 2, c4 = (i & 3) * 4;
            float4 v = *(const float4*)(A + (size_t)(bm + r) * lda + k0 + c4);
            As[c4 + 0][r] = v.x; As[c4 + 1][r] = v.y;
            As[c4 + 2][r] = v.z; As[c4 + 3][r] = v.w;
        }
        {
            int r = tid >> 2, c4 = (tid & 3) * 4;
            float4 v = make_float4(0.f, 0.f, 0.f, 0.f);
            if (bn + r < N)
                v = *(const float4*)(B + (size_t)(bn + r) * ldb + k0 + c4);
            Bs[c4 + 0][r] = v.x; Bs[c4 + 1][r] = v.y;
            Bs[c4 + 2][r] = v.z; Bs[c4 + 3][r] = v.w;
        }
        __syncthreads();
        #pragma unroll
        for (int c = 0; c < 16; c++) {
            float ra[8], rb[4];
            #pragma unroll
            for (int i = 0; i < 8; i++) ra[i] = As[c][ty * 8 + i];
            #pragma unroll
            for (int j = 0; j < 4; j++) rb[j] = Bs[c][tx * 4 + j];
            #pragma unroll
            for (int i = 0; i < 8; i++)
                #pragma unroll
                for (int j = 0; j < 4; j++)
                    acc[i][j] += ra[i] * rb[j];
        }
        __syncthreads();
    }

    #pragma unroll
    for (int i = 0; i < 8; i++) {
        int row = bm + ty * 8 + i;
        #pragma unroll
        for (int j = 0; j < 4; j++) {
            int col = bn + tx * 4 + j;
            if (col < N) {
                float v = acc[i][j] + bias[col];
                C[(size_t)row * ldc + col] = (v > 20.f) ? v : log1pf(__expf(v));
            }
        }
    }
}

// ---------------- depthwise causal conv (K=4) + SiLU (tf32-rounded) ----------
__global__ void conv_silu_kernel(const float* __restrict__ xz, const float* __restrict__ cw,
                                 const float* __restrict__ cb, float* __restrict__ xc) {
    int i = blockIdx.x * blockDim.x + threadIdx.x;
    if (i >= M_ROWS * DI) return;
    int row = i / DI, d = i % DI;
    int b = row / L_SEQ, l = row % L_SEQ;
    float acc = cb[d];
    #pragma unroll
    for (int k = 0; k < KCONV; k++) {
        int ll = l - (KCONV - 1) + k;
        if (ll >= 0)
            acc += cw[d * KCONV + k] * xz[(size_t)(b * L_SEQ + ll) * (2 * DI) + d];
    }
    xc[i] = round_tf32(acc / (1.f + __expf(-acc)));
}

// ---------------- SSM scan (emits tf32-rounded y) ----------------
__global__ void scan_kernel(const float* __restrict__ dt, const float* __restrict__ xc,
                            const float* __restrict__ proj, const float* __restrict__ xz,
                            const float* __restrict__ A_log, const float* __restrict__ Dp,
                            float* __restrict__ y) {
    int gid = (blockIdx.x * blockDim.x + threadIdx.x) >> 4;
    int n = threadIdx.x & 15;
    if (gid >= BATCH * DI) return;
    int b = gid / DI, d = gid % DI;
    float A = -__expf(A_log[d * NSTATE + n]);
    float Dval = Dp[d];
    float h = 0.f;

    size_t row0 = (size_t)b * L_SEQ;
    float dtv = dt[row0 * DI + d];
    float xv  = xc[row0 * DI + d];
    float Bv  = proj[row0 * PROJ_N + RRANK + n];
    float Cv  = proj[row0 * PROJ_N + RRANK + NSTATE + n];

    for (int l = 0; l < L_SEQ; l++) {
        size_t row = row0 + l;
        float ndt = 0.f, nxv = 0.f, nBv = 0.f, nCv = 0.f;
        if (l + 1 < L_SEQ) {
            size_t rn = row + 1;
            ndt = dt[rn * DI + d];
            nxv = xc[rn * DI + d];
            nBv = proj[rn * PROJ_N + RRANK + n];
            nCv = proj[rn * PROJ_N + RRANK + NSTATE + n];
        }
        h = __expf(dtv * A) * h + dtv * Bv * xv;
        float p = h * Cv;
        p += __shfl_xor_sync(0xffffffffu, p, 1);
        p += __shfl_xor_sync(0xffffffffu, p, 2);
        p += __shfl_xor_sync(0xffffffffu, p, 4);
        p += __shfl_xor_sync(0xffffffffu, p, 8);
        if (n == 0) {
            float zv = xz[row * (2 * DI) + DI + d];
            float yv = p + Dval * xv;
            y[row * DI + d] = round_tf32(yv * (zv / (1.f + __expf(-zv))));
        }
        dtv = ndt; xv = nxv; Bv = nBv; Cv = nCv;
    }
}

// ---------------- host orchestration ----------------
extern "C" void kernel_launch(void* const* d_in, const int* in_sizes, int n_in,
                              void* d_out, int out_size) {
    const int*   q_ids   = (const int*)d_in[0];
    const int*   q_mask  = (const int*)d_in[1];
    const float* embed   = (const float*)d_in[4];
    const float* in_w    = (const float*)d_in[5];
    const float* conv_w  = (const float*)d_in[6];
    const float* conv_b  = (const float*)d_in[7];
    const float* x_w     = (const float*)d_in[8];
    const float* dt_w    = (const float*)d_in[9];
    const float* dt_b    = (const float*)d_in[10];
    const float* A_log   = (const float*)d_in[11];
    const float* Dp      = (const float*)d_in[12];
    const float* out_w   = (const float*)d_in[13];
    const float* norm_w  = (const float*)d_in[14];
    const float* fnorm_w = (const float*)d_in[15];
    float* out = (float*)d_out;

    cudaFuncSetAttribute(tf32_gemm_nt<0>, cudaFuncAttributeMaxDynamicSharedMemorySize, MMA_SMEM);
    cudaFuncSetAttribute(tf32_gemm_nt<2>, cudaFuncAttributeMaxDynamicSharedMemorySize, MMA_SMEM);

    float *h, *r, *xz, *xc, *proj, *dt, *y;
    cudaGetSymbolAddress((void**)&h,    g_h);
    cudaGetSymbolAddress((void**)&r,    g_r);
    cudaGetSymbolAddress((void**)&xz,   g_xz);
    cudaGetSymbolAddress((void**)&xc,   g_xc);
    cudaGetSymbolAddress((void**)&proj, g_proj);
    cudaGetSymbolAddress((void**)&dt,   g_dt);
    cudaGetSymbolAddress((void**)&y,    g_y);

    embed_kernel<<<(M_ROWS * DM + 255) / 256, 256>>>(q_ids, q_mask, embed, h);

    for (int l = 0; l < NLAYER; l++) {
        const float* in_w_l  = in_w  + (size_t)l * (2 * DI) * DM;
        const float* cw_l    = conv_w + (size_t)l * DI * KCONV;
        const float* cb_l    = conv_b + (size_t)l * DI;
        const float* x_w_l   = x_w   + (size_t)l * PROJ_N * DI;
        const float* dt_w_l  = dt_w  + (size_t)l * DI * RRANK;
        const float* dt_b_l  = dt_b  + (size_t)l * DI;
        const float* A_log_l = A_log + (size_t)l * DI * NSTATE;
        const float* Dp_l    = Dp    + (size_t)l * DI;
        const float* out_w_l = out_w + (size_t)l * DM * DI;
        const float* norm_l  = norm_w + (size_t)l * DM;

        rmsnorm_kernel<<<M_ROWS, 256>>>(h, norm_l, r);

        // xz = r @ in_w^T  (1024 x 3072, K=768)
        tf32_gemm_nt<0><<<dim3(M_ROWS / 128, (2 * DI + 127) / 128, 1), 256, MMA_SMEM>>>(
            r, in_w_l, xz, 2 * DI, DM, DM, DM, 2 * DI);

        conv_silu_kernel<<<(M_ROWS * DI + 255) / 256, 256>>>(xz, cw_l, cb_l, xc);

        // proj = xc @ x_w^T  (1024 x 80, K=1536) — split-K x8, atomic
        zero_kernel<<<(M_ROWS * PROJ_N + 255) / 256, 256>>>(proj, M_ROWS * PROJ_N);
        tf32_gemm_nt<2><<<dim3(M_ROWS / 128, 1, 8), 256, MMA_SMEM>>>(
            xc, x_w_l, proj, PROJ_N, DI / 8, DI, DI, PROJ_N);

        // dt = softplus(proj[:, :48] @ dt_w^T + dt_b)  (1024 x 1536, K=48)
        sgemm_nt_softplus<<<dim3((DI + 63) / 64, M_ROWS / 128), 256>>>(
            proj, dt_w_l, dt, dt_b_l, M_ROWS, DI, RRANK, PROJ_N, RRANK, DI);

        scan_kernel<<<(BATCH * DI * 16 + 255) / 256, 256>>>(
            dt, xc, proj, xz, A_log_l, Dp_l, y);

        // h += y @ out_w^T  (1024 x 768, K=1536) — split-K x4, atomic into residual
        tf32_gemm_nt<2><<<dim3(M_ROWS / 128, DM / 128, 4), 256, MMA_SMEM>>>(
            y, out_w_l, h, DM, DI / 4, DI, DI, DM);
    }

    rmsnorm_kernel<<<M_ROWS, 256>>>(h, fnorm_w, r);

    // logits = r @ embed^T  (1024 x 50280, K=768)
    tf32_gemm_nt<0><<<dim3(M_ROWS / 128, (VOCAB + 127) / 128, 1), 256, MMA_SMEM>>>(
        r, embed, out, VOCAB, DM, DM, DM, VOCAB);
}